// round 16
// baseline (speedup 1.0000x reference)
#include <cuda_runtime.h>

#define BATCH 131072
#define NNEI 20
#define NFEAT 172
#define NTIME 100

// ---- scratch (device globals; no allocations) ----
__device__ float g_qs[(size_t)BATCH * 100];      // scaled q
__device__ float g_A[(size_t)BATCH * 576];       // folded score rows: head h at h*288, bias col 272, cols 273+ zero
__device__ float g_m[(size_t)BATCH * 544];       // weighted kv sums
__device__ unsigned char g_invalid[BATCH];
__device__ float g_W1[100 * 128];                // Wq^T, padded cols
__device__ float g_Wke2[2 * 50 * 320];           // per-head Wk (+bk col 272), padded to 320 cols
__device__ float g_Pv[544 * 128];                // folded Wo@Wv, padded cols
__device__ float g_bo2[128];                     // folded Wo@bv + bo
__device__ int g_maskmode;                       // 0=int32, 1=uint8, 2=float32

// ---- packed f32x2 helpers ----
__device__ __forceinline__ void fma2(unsigned long long& d, unsigned long long a, unsigned long long b) {
    asm("fma.rn.f32x2 %0, %1, %2, %0;" : "+l"(d) : "l"(a), "l"(b));
}
__device__ __forceinline__ unsigned long long pk2(float x, float y) {
    unsigned long long r; asm("mov.b64 %0, {%1,%2};" : "=l"(r) : "f"(x), "f"(y)); return r;
}
__device__ __forceinline__ float2 upk2(unsigned long long v) {
    float2 r; asm("mov.b64 {%0,%1}, %2;" : "=f"(r.x), "=f"(r.y) : "l"(v)); return r;
}

// ---------------- setup: folded weights + mask dtype detection (block 0) ----------------
__global__ void setup_kernel(const float* __restrict__ Wq, const float* __restrict__ Wk,
                             const float* __restrict__ Wv, const float* __restrict__ b_in,
                             const float* __restrict__ Wo, const float* __restrict__ bo,
                             const unsigned int* __restrict__ maskw) {
    int idx = blockIdx.x * blockDim.x + threadIdx.x;
    if (blockIdx.x == 0) {             // mask dtype detection
        __shared__ int s_word_not01, s_byte_not01;
        if (threadIdx.x == 0) { s_word_not01 = 0; s_byte_not01 = 0; }
        __syncthreads();
        int bad_w = 0, bad_b = 0;
        for (int i = threadIdx.x; i < 1024; i += 256) {
            unsigned v = maskw[i];
            if (v > 1u) bad_w = 1;
            #pragma unroll
            for (int b = 0; b < 4; b++) {
                unsigned by = (v >> (8 * b)) & 0xffu;
                if (by > 1u) bad_b = 1;
            }
        }
        if (bad_w) atomicOr(&s_word_not01, 1);
        if (bad_b) atomicOr(&s_byte_not01, 1);
        __syncthreads();
        if (threadIdx.x == 0)
            g_maskmode = (s_word_not01 == 0) ? 0 : ((s_byte_not01 == 0) ? 1 : 2);
    }
    if (idx < 12800) {                 // W1[t][col] = Wq[col][t]
        int t = idx >> 7, col = idx & 127;
        g_W1[idx] = (col < 100) ? Wq[col * 100 + t] : 0.f;
    }
    if (idx < 32000) {                 // Wke2[h][k][c]
        int h = idx / 16000, rem = idx % 16000;
        int k = rem / 320, c = rem % 320;
        int kg = h * 50 + k;
        float v = 0.f;
        if (c < 272) v = Wk[kg * 272 + c];
        else if (c == 272) v = b_in[100 + kg];
        g_Wke2[idx] = v;
    }
    if (idx < 128) {                   // bo2 = Wo @ bv + bo
        float v = 0.f;
        if (idx < 100) {
            v = bo[idx];
            for (int j = 0; j < 100; j++) v += Wo[idx * 100 + j] * b_in[200 + j];
        }
        g_bo2[idx] = v;
    }
    if (idx < 69632) {                 // Pv[h*272+c][i] = sum_j Wo[i, h*50+j] * Wv[h*50+j, c]
        int kk = idx >> 7, i = idx & 127;
        int h = kk / 272, c = kk % 272;
        float v = 0.f;
        if (i < 100) {
            #pragma unroll 5
            for (int j = 0; j < 50; j++)
                v += Wo[i * 100 + h * 50 + j] * Wv[(h * 50 + j) * 272 + c];
        }
        g_Pv[idx] = v;
    }
}

// ---------------- K1: qs = (st @ Wq^T + bq) * d^-0.5 ; 8 batches/warp, f32x2 ----------------
__global__ __launch_bounds__(256, 2) void k1_qproj(const float* __restrict__ st,
                                                   const float* __restrict__ b_in) {
    extern __shared__ float sm[];
    float* Ws = sm;                    // 100*128
    int tid = threadIdx.x;
    for (int i = tid; i < 12800 / 4; i += 256)
        ((float4*)Ws)[i] = ((const float4*)g_W1)[i];
    __syncthreads();
    int warp = tid >> 5, lane = tid & 31;
    size_t b0 = (size_t)blockIdx.x * 64 + warp * 8;
    unsigned long long acc[8][2];
    #pragma unroll
    for (int i = 0; i < 8; i++) { acc[i][0] = 0ull; acc[i][1] = 0ull; }
    int wbase = lane * 2;
    #pragma unroll 1
    for (int k = 0; k < 100; k += 4) {
        float4 xv[8];
        #pragma unroll
        for (int i = 0; i < 8; i++)
            xv[i] = *(const float4*)(st + (b0 + i) * 100 + k);
        #pragma unroll
        for (int q = 0; q < 4; q++) {
            unsigned long long w0 = *(const unsigned long long*)&Ws[(k + q) * 128 + wbase];
            unsigned long long w1 = *(const unsigned long long*)&Ws[(k + q) * 128 + wbase + 64];
            #pragma unroll
            for (int i = 0; i < 8; i++) {
                float x = (q == 0) ? xv[i].x : (q == 1) ? xv[i].y : (q == 2) ? xv[i].z : xv[i].w;
                unsigned long long xd = pk2(x, x);
                fma2(acc[i][0], xd, w0);
                fma2(acc[i][1], xd, w1);
            }
        }
    }
    const float dscale = 0.14142135623730951f;   // 1/sqrt(50)
    #pragma unroll
    for (int u = 0; u < 2; u++) {
        int c0 = lane * 2 + 64 * u;
        if (c0 < 100) {
            float bx = b_in[c0];
            float by = (c0 + 1 < 100) ? b_in[c0 + 1] : 0.f;
            #pragma unroll
            for (int i = 0; i < 8; i++) {
                float2 v = upk2(acc[i][u]);
                v.x = (v.x + bx) * dscale;
                v.y = (v.y + by) * dscale;
                if (c0 + 1 < 100)
                    *(float2*)(g_qs + (b0 + i) * 100 + c0) = v;
                else
                    g_qs[(b0 + i) * 100 + c0] = v.x;
            }
        }
    }
}

// ---------------- K2: A[b][h*288+c] = sum_k qs[b,h*50+k] * Wke2[h][k][c]; x staged in smem ----------------
__global__ __launch_bounds__(256, 3) void k2_aproj() {
    extern __shared__ float sm[];
    float* Ws = sm;                    // 50*320 = 16000
    float* xs = sm + 16000;            // 32*50  = 1600
    int tid = threadIdx.x;
    int h = blockIdx.y;
    size_t B0 = (size_t)blockIdx.x * 32;
    for (int i = tid; i < 16000 / 4; i += 256)
        ((float4*)Ws)[i] = ((const float4*)(g_Wke2 + h * 16000))[i];
    for (int i = tid; i < 1600; i += 256) {
        int bi = i / 50, c = i % 50;
        xs[i] = g_qs[(B0 + bi) * 100 + h * 50 + c];
    }
    __syncthreads();
    int warp = tid >> 5, lane = tid & 31;
    int lb = warp * 4;
    size_t b0 = B0 + lb;
    unsigned long long acc[4][5];
    #pragma unroll
    for (int i = 0; i < 4; i++)
        #pragma unroll
        for (int u = 0; u < 5; u++) acc[i][u] = 0ull;
    int wbase = lane * 2;
    #pragma unroll 1
    for (int k = 0; k < 50; k += 2) {
        float2 xv[4];
        #pragma unroll
        for (int i = 0; i < 4; i++)
            xv[i] = *(const float2*)&xs[(lb + i) * 50 + k];
        #pragma unroll
        for (int q = 0; q < 2; q++) {
            unsigned long long w2[5];
            #pragma unroll
            for (int u = 0; u < 5; u++)
                w2[u] = *(const unsigned long long*)&Ws[(k + q) * 320 + wbase + 64 * u];
            #pragma unroll
            for (int i = 0; i < 4; i++) {
                float x = q ? xv[i].y : xv[i].x;
                unsigned long long xd = pk2(x, x);
                #pragma unroll
                for (int u = 0; u < 5; u++) fma2(acc[i][u], xd, w2[u]);
            }
        }
    }
    #pragma unroll
    for (int u = 0; u < 5; u++) {
        int c0 = lane * 2 + 64 * u;
        #pragma unroll
        for (int i = 0; i < 4; i++) {
            float2 v = upk2(acc[i][u]);
            float* Ar = g_A + (b0 + i) * 576 + h * 288;
            if (c0 < 273) Ar[c0] = v.x;
            if (c0 + 1 < 273) Ar[c0 + 1] = v.y;
        }
    }
}

// ---- kv pair loader: 5 float2 column-pairs at c0 = lane*2 (+64u); kv[272]=1 for bias ----
__device__ __forceinline__ void load_kv5(const float* __restrict__ nr, const float* __restrict__ tr,
                                         int wbase, unsigned long long* kv) {
    float2 v;
    v = *(const float2*)(nr + wbase);                 kv[0] = pk2(v.x, v.y);
    v = *(const float2*)(nr + wbase + 64);            kv[1] = pk2(v.x, v.y);
    v = (wbase + 128 < NFEAT) ? *(const float2*)(nr + wbase + 128)
                              : *(const float2*)(tr + wbase + 128 - NFEAT);
    kv[2] = pk2(v.x, v.y);
    v = *(const float2*)(tr + wbase + 192 - NFEAT);   kv[3] = pk2(v.x, v.y);
    int c4 = wbase + 256;
    if (c4 < 272)       v = *(const float2*)(tr + c4 - NFEAT);
    else if (c4 == 272) { v.x = 1.f; v.y = 0.f; }
    else                { v.x = 0.f; v.y = 0.f; }
    kv[4] = pk2(v.x, v.y);
}

// ---------------- K3: attention, two-phase (scores -> warp softmax -> weighted sum) ----------------
__global__ __launch_bounds__(128, 4) void k3_attn(const float* __restrict__ nf,
                                                  const float* __restrict__ ntf,
                                                  const void* __restrict__ maskp,
                                                  float* __restrict__ d_out) {
    int warp = threadIdx.x >> 5, lane = threadIdx.x & 31;
    size_t b = (size_t)blockIdx.x * 4 + warp;
    int wbase = lane * 2;

    // mask -> validbits
    int mode = g_maskmode;
    bool masked = true;
    if (lane < 20) {
        size_t mi = b * 20 + lane;
        if (mode == 0)      masked = ((const int*)maskp)[mi] != 0;
        else if (mode == 1) masked = ((const unsigned char*)maskp)[mi] != 0;
        else                masked = ((const float*)maskp)[mi] != 0.f;
    }
    unsigned validbits = __ballot_sync(0xffffffffu, (lane < 20) && !masked);
    float* wavg = d_out + (size_t)BATCH * 100 + b * 20;
    if (validbits == 0) {
        if (lane == 0) g_invalid[b] = 1;
        if (lane < 20) wavg[lane] = 0.f;
        return;
    }
    if (lane == 0) g_invalid[b] = 0;

    // A rows (bias folded at col 272; cols >272 zero -> guarded)
    const float* Ab = g_A + b * 576;
    unsigned long long aA0[5], aA1[5];
    #pragma unroll
    for (int u = 0; u < 5; u++) {
        int c0 = wbase + 64 * u;
        if (c0 <= 272) {
            float2 v0 = *(const float2*)(Ab + c0);
            float2 v1 = *(const float2*)(Ab + 288 + c0);
            aA0[u] = pk2(v0.x, v0.y);
            aA1[u] = pk2(v1.x, v1.y);
        } else {
            aA0[u] = 0ull;
            aA1[u] = 0ull;
        }
    }

    const float NEGINF = -__int_as_float(0x7f800000);
    float s0 = NEGINF, s1 = NEGINF;    // lane n holds score of neighbor n

    // ---- phase 1: scores (no cross-neighbor dependence), depth-1 prefetch ----
    {
        unsigned rem = validbits;
        int n = __ffs(rem) - 1;
        rem &= rem - 1;
        unsigned long long kv2[5];
        load_kv5(nf + (b * NNEI + n) * NFEAT, ntf + (b * NNEI + n) * NTIME, wbase, kv2);
        while (true) {
            int nn = rem ? (__ffs(rem) - 1) : -1;
            unsigned long long nx[5];
            if (nn >= 0) {
                load_kv5(nf + (b * NNEI + nn) * NFEAT, ntf + (b * NNEI + nn) * NTIME, wbase, nx);
                rem &= rem - 1;
            }
            unsigned long long pp0 = 0ull, pp1 = 0ull;
            #pragma unroll
            for (int u = 0; u < 5; u++) { fma2(pp0, aA0[u], kv2[u]); fma2(pp1, aA1[u], kv2[u]); }
            float2 P0 = upk2(pp0), P1 = upk2(pp1);
            float p0 = P0.x + P0.y, p1 = P1.x + P1.y;
            #pragma unroll
            for (int o = 16; o; o >>= 1) {
                p0 += __shfl_xor_sync(0xffffffffu, p0, o);
                p1 += __shfl_xor_sync(0xffffffffu, p1, o);
            }
            if (lane == n) { s0 = p0; s1 = p1; }
            if (nn < 0) break;
            n = nn;
            #pragma unroll
            for (int u = 0; u < 5; u++) kv2[u] = nx[u];
        }
    }

    // ---- warp softmax over per-lane scores ----
    float m0 = s0, m1 = s1;
    #pragma unroll
    for (int o = 16; o; o >>= 1) {
        m0 = fmaxf(m0, __shfl_xor_sync(0xffffffffu, m0, o));
        m1 = fmaxf(m1, __shfl_xor_sync(0xffffffffu, m1, o));
    }
    float e0 = __expf(s0 - m0), e1 = __expf(s1 - m1);
    float Z0 = e0, Z1 = e1;
    #pragma unroll
    for (int o = 16; o; o >>= 1) {
        Z0 += __shfl_xor_sync(0xffffffffu, Z0, o);
        Z1 += __shfl_xor_sync(0xffffffffu, Z1, o);
    }
    float w0 = e0 * (1.f / Z0), w1 = e1 * (1.f / Z1);
    if (lane < 20)
        wavg[lane] = 0.5f * (w0 + w1);

    // ---- phase 2: weighted sum (kv reloads hit L1/L2); no final divide ----
    unsigned long long av0[5], av1[5];
    #pragma unroll
    for (int u = 0; u < 5; u++) { av0[u] = 0ull; av1[u] = 0ull; }
    unsigned rem = validbits;
    while (rem) {
        int n = __ffs(rem) - 1;
        rem &= rem - 1;
        float a = __shfl_sync(0xffffffffu, w0, n);
        float c = __shfl_sync(0xffffffffu, w1, n);
        unsigned long long kv2[5];
        load_kv5(nf + (b * NNEI + n) * NFEAT, ntf + (b * NNEI + n) * NTIME, wbase, kv2);
        unsigned long long ad = pk2(a, a), cd = pk2(c, c);
        #pragma unroll
        for (int u = 0; u < 5; u++) { fma2(av0[u], ad, kv2[u]); fma2(av1[u], cd, kv2[u]); }
    }

    float* mb = g_m + b * 544;
    #pragma unroll
    for (int u = 0; u < 5; u++) {
        int c0 = wbase + 64 * u;
        if (c0 < 272) {
            *(float2*)(mb + c0) = upk2(av0[u]);
            *(float2*)(mb + 272 + c0) = upk2(av1[u]);
        }
    }
}

// ---------------- K4: out = m @ Pv + bo2; 8 batches/warp; 8 k-tiles of 68 -> 3 CTAs/SM ----------------
__global__ __launch_bounds__(256, 3) void k4_out(float* __restrict__ d_out) {
    extern __shared__ float sm[];
    float* Pvs = sm;                   // 68*128 = 8704 floats (k-tile of Pv)
    float* ms  = sm + 8704;            // 64*68  = 4352 floats (k-tile of m)
    int tid = threadIdx.x;
    int warp = tid >> 5, lane = tid & 31;
    size_t B0 = (size_t)blockIdx.x * 64;
    int lb = warp * 8;
    size_t b0 = B0 + lb;
    unsigned long long acc[8][2];
    #pragma unroll
    for (int i = 0; i < 8; i++) { acc[i][0] = 0ull; acc[i][1] = 0ull; }
    int wbase = lane * 2;
    #pragma unroll 1
    for (int kt = 0; kt < 8; kt++) {
        if (kt) __syncthreads();
        {   // stage Pv k-tile (68 rows x 128 cols)
            const float4* src = (const float4*)(g_Pv + kt * 68 * 128);
            for (int i = tid; i < 68 * 128 / 4; i += 256)
                ((float4*)Pvs)[i] = src[i];
        }
        {   // stage m k-tile (64 batches x 68 cols)
            for (int i = tid; i < 64 * 17; i += 256) {
                int bi = i / 17, c4 = i % 17;
                ((float4*)ms)[bi * 17 + c4] =
                    *(const float4*)(g_m + (B0 + bi) * 544 + kt * 68 + c4 * 4);
            }
        }
        __syncthreads();
        #pragma unroll 2
        for (int k = 0; k < 68; k += 2) {
            float2 xv[8];
            #pragma unroll
            for (int i = 0; i < 8; i++)
                xv[i] = *(const float2*)&ms[(lb + i) * 68 + k];
            #pragma unroll
            for (int q = 0; q < 2; q++) {
                unsigned long long w0 = *(const unsigned long long*)&Pvs[(k + q) * 128 + wbase];
                unsigned long long w1 = *(const unsigned long long*)&Pvs[(k + q) * 128 + wbase + 64];
                #pragma unroll
                for (int i = 0; i < 8; i++) {
                    float x = q ? xv[i].y : xv[i].x;
                    unsigned long long xd = pk2(x, x);
                    fma2(acc[i][0], xd, w0);
                    fma2(acc[i][1], xd, w1);
                }
            }
        }
    }
    #pragma unroll
    for (int u = 0; u < 2; u++) {
        int c0 = lane * 2 + 64 * u;
        if (c0 < 100) {
            float bx = g_bo2[c0];
            float by = (c0 + 1 < 100) ? g_bo2[c0 + 1] : 0.f;
            #pragma unroll
            for (int i = 0; i < 8; i++) {
                float2 v = upk2(acc[i][u]);
                bool inv = g_invalid[b0 + i];
                v.x = inv ? 0.f : (v.x + bx);
                v.y = inv ? 0.f : (v.y + by);
                if (c0 + 1 < 100)
                    *(float2*)(d_out + (b0 + i) * 100 + c0) = v;
                else
                    d_out[(b0 + i) * 100 + c0] = v.x;
            }
        }
    }
}

extern "C" void kernel_launch(void* const* d_in, const int* in_sizes, int n_in,
                              void* d_out, int out_size) {
    (void)in_sizes; (void)n_in; (void)out_size;
    const float* st   = (const float*)d_in[0];
    const float* nf   = (const float*)d_in[1];
    const float* ntf  = (const float*)d_in[2];
    const void*  mask = d_in[3];
    const float* Wq   = (const float*)d_in[4];
    const float* Wk   = (const float*)d_in[5];
    const float* Wv   = (const float*)d_in[6];
    const float* b_in = (const float*)d_in[7];
    const float* Wo   = (const float*)d_in[8];
    const float* bo   = (const float*)d_in[9];
    float* out = (float*)d_out;

    cudaFuncSetAttribute(k1_qproj, cudaFuncAttributeMaxDynamicSharedMemorySize, 51200);
    cudaFuncSetAttribute(k2_aproj, cudaFuncAttributeMaxDynamicSharedMemorySize, 70400);
    cudaFuncSetAttribute(k4_out,   cudaFuncAttributeMaxDynamicSharedMemorySize, 52224);

    setup_kernel<<<272, 256>>>(Wq, Wk, Wv, b_in, Wo, bo, (const unsigned int*)mask);
    k1_qproj<<<BATCH / 64, 256, 51200>>>(st, b_in);
    k2_aproj<<<dim3(BATCH / 32, 2), 256, 70400>>>();
    k3_attn<<<BATCH / 4, 128>>>(nf, ntf, mask, out);
    k4_out<<<BATCH / 64, 256, 52224>>>(out);
}

// round 17
// speedup vs baseline: 1.0694x; 1.0694x over previous
#include <cuda_runtime.h>

#define BATCH 131072
#define NNEI 20
#define NFEAT 172
#define NTIME 100

// ---- scratch (device globals; no allocations) ----
__device__ float g_qs[(size_t)BATCH * 100];      // scaled q
__device__ float g_A[(size_t)BATCH * 576];       // folded score rows: head h at h*288, bias col 272, cols 273+ zero
__device__ float g_m[(size_t)BATCH * 544];       // weighted kv sums
__device__ unsigned char g_invalid[BATCH];
__device__ float g_W1[100 * 128];                // Wq^T, padded cols
__device__ float g_Wke2[2 * 50 * 320];           // per-head Wk (+bk col 272), padded to 320 cols
__device__ float g_Pv[544 * 128];                // folded Wo@Wv, padded cols
__device__ float g_bo2[128];                     // folded Wo@bv + bo
__device__ int g_maskmode;                       // 0=int32, 1=uint8, 2=float32

// ---- packed f32x2 helpers ----
__device__ __forceinline__ void fma2(unsigned long long& d, unsigned long long a, unsigned long long b) {
    asm("fma.rn.f32x2 %0, %1, %2, %0;" : "+l"(d) : "l"(a), "l"(b));
}
__device__ __forceinline__ unsigned long long pk2(float x, float y) {
    unsigned long long r; asm("mov.b64 %0, {%1,%2};" : "=l"(r) : "f"(x), "f"(y)); return r;
}
__device__ __forceinline__ float2 upk2(unsigned long long v) {
    float2 r; asm("mov.b64 {%0,%1}, %2;" : "=f"(r.x), "=f"(r.y) : "l"(v)); return r;
}

// ---------------- setup: folded weights + mask dtype detection (block 0) ----------------
__global__ void setup_kernel(const float* __restrict__ Wq, const float* __restrict__ Wk,
                             const float* __restrict__ Wv, const float* __restrict__ b_in,
                             const float* __restrict__ Wo, const float* __restrict__ bo,
                             const unsigned int* __restrict__ maskw) {
    int idx = blockIdx.x * blockDim.x + threadIdx.x;
    if (blockIdx.x == 0) {             // mask dtype detection
        __shared__ int s_word_not01, s_byte_not01;
        if (threadIdx.x == 0) { s_word_not01 = 0; s_byte_not01 = 0; }
        __syncthreads();
        int bad_w = 0, bad_b = 0;
        for (int i = threadIdx.x; i < 1024; i += 256) {
            unsigned v = maskw[i];
            if (v > 1u) bad_w = 1;
            #pragma unroll
            for (int b = 0; b < 4; b++) {
                unsigned by = (v >> (8 * b)) & 0xffu;
                if (by > 1u) bad_b = 1;
            }
        }
        if (bad_w) atomicOr(&s_word_not01, 1);
        if (bad_b) atomicOr(&s_byte_not01, 1);
        __syncthreads();
        if (threadIdx.x == 0)
            g_maskmode = (s_word_not01 == 0) ? 0 : ((s_byte_not01 == 0) ? 1 : 2);
    }
    if (idx < 12800) {                 // W1[t][col] = Wq[col][t]
        int t = idx >> 7, col = idx & 127;
        g_W1[idx] = (col < 100) ? Wq[col * 100 + t] : 0.f;
    }
    if (idx < 32000) {                 // Wke2[h][k][c]
        int h = idx / 16000, rem = idx % 16000;
        int k = rem / 320, c = rem % 320;
        int kg = h * 50 + k;
        float v = 0.f;
        if (c < 272) v = Wk[kg * 272 + c];
        else if (c == 272) v = b_in[100 + kg];
        g_Wke2[idx] = v;
    }
    if (idx < 128) {                   // bo2 = Wo @ bv + bo
        float v = 0.f;
        if (idx < 100) {
            v = bo[idx];
            for (int j = 0; j < 100; j++) v += Wo[idx * 100 + j] * b_in[200 + j];
        }
        g_bo2[idx] = v;
    }
    if (idx < 69632) {                 // Pv[h*272+c][i] = sum_j Wo[i, h*50+j] * Wv[h*50+j, c]
        int kk = idx >> 7, i = idx & 127;
        int h = kk / 272, c = kk % 272;
        float v = 0.f;
        if (i < 100) {
            #pragma unroll 5
            for (int j = 0; j < 50; j++)
                v += Wo[i * 100 + h * 50 + j] * Wv[(h * 50 + j) * 272 + c];
        }
        g_Pv[idx] = v;
    }
}

// ---------------- K1: qs = (st @ Wq^T + bq) * d^-0.5 ; 8 batches/warp, f32x2 ----------------
__global__ __launch_bounds__(256, 2) void k1_qproj(const float* __restrict__ st,
                                                   const float* __restrict__ b_in) {
    extern __shared__ float sm[];
    float* Ws = sm;                    // 100*128
    int tid = threadIdx.x;
    for (int i = tid; i < 12800 / 4; i += 256)
        ((float4*)Ws)[i] = ((const float4*)g_W1)[i];
    __syncthreads();
    int warp = tid >> 5, lane = tid & 31;
    size_t b0 = (size_t)blockIdx.x * 64 + warp * 8;
    unsigned long long acc[8][2];
    #pragma unroll
    for (int i = 0; i < 8; i++) { acc[i][0] = 0ull; acc[i][1] = 0ull; }
    int wbase = lane * 2;
    #pragma unroll 1
    for (int k = 0; k < 100; k += 4) {
        float4 xv[8];
        #pragma unroll
        for (int i = 0; i < 8; i++)
            xv[i] = *(const float4*)(st + (b0 + i) * 100 + k);
        #pragma unroll
        for (int q = 0; q < 4; q++) {
            unsigned long long w0 = *(const unsigned long long*)&Ws[(k + q) * 128 + wbase];
            unsigned long long w1 = *(const unsigned long long*)&Ws[(k + q) * 128 + wbase + 64];
            #pragma unroll
            for (int i = 0; i < 8; i++) {
                float x = (q == 0) ? xv[i].x : (q == 1) ? xv[i].y : (q == 2) ? xv[i].z : xv[i].w;
                unsigned long long xd = pk2(x, x);
                fma2(acc[i][0], xd, w0);
                fma2(acc[i][1], xd, w1);
            }
        }
    }
    const float dscale = 0.14142135623730951f;   // 1/sqrt(50)
    #pragma unroll
    for (int u = 0; u < 2; u++) {
        int c0 = lane * 2 + 64 * u;
        if (c0 < 100) {
            float bx = b_in[c0];
            float by = (c0 + 1 < 100) ? b_in[c0 + 1] : 0.f;
            #pragma unroll
            for (int i = 0; i < 8; i++) {
                float2 v = upk2(acc[i][u]);
                v.x = (v.x + bx) * dscale;
                v.y = (v.y + by) * dscale;
                if (c0 + 1 < 100)
                    *(float2*)(g_qs + (b0 + i) * 100 + c0) = v;
                else
                    g_qs[(b0 + i) * 100 + c0] = v.x;
            }
        }
    }
}

// ---------------- K2: A[b][h*288+c] = sum_k qs[b,h*50+k] * Wke2[h][k][c]; x staged in smem ----------------
__global__ __launch_bounds__(256, 3) void k2_aproj() {
    extern __shared__ float sm[];
    float* Ws = sm;                    // 50*320 = 16000
    float* xs = sm + 16000;            // 32*50  = 1600
    int tid = threadIdx.x;
    int h = blockIdx.y;
    size_t B0 = (size_t)blockIdx.x * 32;
    for (int i = tid; i < 16000 / 4; i += 256)
        ((float4*)Ws)[i] = ((const float4*)(g_Wke2 + h * 16000))[i];
    for (int i = tid; i < 1600; i += 256) {
        int bi = i / 50, c = i % 50;
        xs[i] = g_qs[(B0 + bi) * 100 + h * 50 + c];
    }
    __syncthreads();
    int warp = tid >> 5, lane = tid & 31;
    int lb = warp * 4;
    size_t b0 = B0 + lb;
    unsigned long long acc[4][5];
    #pragma unroll
    for (int i = 0; i < 4; i++)
        #pragma unroll
        for (int u = 0; u < 5; u++) acc[i][u] = 0ull;
    int wbase = lane * 2;
    #pragma unroll 1
    for (int k = 0; k < 50; k += 2) {
        float2 xv[4];
        #pragma unroll
        for (int i = 0; i < 4; i++)
            xv[i] = *(const float2*)&xs[(lb + i) * 50 + k];
        #pragma unroll
        for (int q = 0; q < 2; q++) {
            unsigned long long w2[5];
            #pragma unroll
            for (int u = 0; u < 5; u++)
                w2[u] = *(const unsigned long long*)&Ws[(k + q) * 320 + wbase + 64 * u];
            #pragma unroll
            for (int i = 0; i < 4; i++) {
                float x = q ? xv[i].y : xv[i].x;
                unsigned long long xd = pk2(x, x);
                #pragma unroll
                for (int u = 0; u < 5; u++) fma2(acc[i][u], xd, w2[u]);
            }
        }
    }
    #pragma unroll
    for (int u = 0; u < 5; u++) {
        int c0 = lane * 2 + 64 * u;
        #pragma unroll
        for (int i = 0; i < 4; i++) {
            float2 v = upk2(acc[i][u]);
            float* Ar = g_A + (b0 + i) * 576 + h * 288;
            if (c0 < 273) Ar[c0] = v.x;
            if (c0 + 1 < 273) Ar[c0 + 1] = v.y;
        }
    }
}

// ---- kv pair loader: 5 float2 column-pairs at c0 = lane*2 (+64u); kv[272]=1 for bias ----
__device__ __forceinline__ void load_kv5(const float* __restrict__ nr, const float* __restrict__ tr,
                                         int wbase, unsigned long long* kv) {
    float2 v;
    v = *(const float2*)(nr + wbase);                 kv[0] = pk2(v.x, v.y);
    v = *(const float2*)(nr + wbase + 64);            kv[1] = pk2(v.x, v.y);
    v = (wbase + 128 < NFEAT) ? *(const float2*)(nr + wbase + 128)
                              : *(const float2*)(tr + wbase + 128 - NFEAT);
    kv[2] = pk2(v.x, v.y);
    v = *(const float2*)(tr + wbase + 192 - NFEAT);   kv[3] = pk2(v.x, v.y);
    int c4 = wbase + 256;
    if (c4 < 272)       v = *(const float2*)(tr + c4 - NFEAT);
    else if (c4 == 272) { v.x = 1.f; v.y = 0.f; }
    else                { v.x = 0.f; v.y = 0.f; }
    kv[4] = pk2(v.x, v.y);
}

// ---------------- K3: attention, two-phase (scores -> warp softmax -> weighted sum) ----------------
__global__ __launch_bounds__(128, 4) void k3_attn(const float* __restrict__ nf,
                                                  const float* __restrict__ ntf,
                                                  const void* __restrict__ maskp,
                                                  float* __restrict__ d_out) {
    int warp = threadIdx.x >> 5, lane = threadIdx.x & 31;
    size_t b = (size_t)blockIdx.x * 4 + warp;
    int wbase = lane * 2;

    // mask -> validbits
    int mode = g_maskmode;
    bool masked = true;
    if (lane < 20) {
        size_t mi = b * 20 + lane;
        if (mode == 0)      masked = ((const int*)maskp)[mi] != 0;
        else if (mode == 1) masked = ((const unsigned char*)maskp)[mi] != 0;
        else                masked = ((const float*)maskp)[mi] != 0.f;
    }
    unsigned validbits = __ballot_sync(0xffffffffu, (lane < 20) && !masked);
    float* wavg = d_out + (size_t)BATCH * 100 + b * 20;
    if (validbits == 0) {
        if (lane == 0) g_invalid[b] = 1;
        if (lane < 20) wavg[lane] = 0.f;
        return;
    }
    if (lane == 0) g_invalid[b] = 0;

    // A rows (bias folded at col 272; cols >272 zero -> guarded)
    const float* Ab = g_A + b * 576;
    unsigned long long aA0[5], aA1[5];
    #pragma unroll
    for (int u = 0; u < 5; u++) {
        int c0 = wbase + 64 * u;
        if (c0 <= 272) {
            float2 v0 = *(const float2*)(Ab + c0);
            float2 v1 = *(const float2*)(Ab + 288 + c0);
            aA0[u] = pk2(v0.x, v0.y);
            aA1[u] = pk2(v1.x, v1.y);
        } else {
            aA0[u] = 0ull;
            aA1[u] = 0ull;
        }
    }

    const float NEGINF = -__int_as_float(0x7f800000);
    float s0 = NEGINF, s1 = NEGINF;    // lane n holds score of neighbor n

    // ---- phase 1: scores (no cross-neighbor dependence), depth-1 prefetch ----
    {
        unsigned rem = validbits;
        int n = __ffs(rem) - 1;
        rem &= rem - 1;
        unsigned long long kv2[5];
        load_kv5(nf + (b * NNEI + n) * NFEAT, ntf + (b * NNEI + n) * NTIME, wbase, kv2);
        while (true) {
            int nn = rem ? (__ffs(rem) - 1) : -1;
            unsigned long long nx[5];
            if (nn >= 0) {
                load_kv5(nf + (b * NNEI + nn) * NFEAT, ntf + (b * NNEI + nn) * NTIME, wbase, nx);
                rem &= rem - 1;
            }
            unsigned long long pp0 = 0ull, pp1 = 0ull;
            #pragma unroll
            for (int u = 0; u < 5; u++) { fma2(pp0, aA0[u], kv2[u]); fma2(pp1, aA1[u], kv2[u]); }
            float2 P0 = upk2(pp0), P1 = upk2(pp1);
            float p0 = P0.x + P0.y, p1 = P1.x + P1.y;
            #pragma unroll
            for (int o = 16; o; o >>= 1) {
                p0 += __shfl_xor_sync(0xffffffffu, p0, o);
                p1 += __shfl_xor_sync(0xffffffffu, p1, o);
            }
            if (lane == n) { s0 = p0; s1 = p1; }
            if (nn < 0) break;
            n = nn;
            #pragma unroll
            for (int u = 0; u < 5; u++) kv2[u] = nx[u];
        }
    }

    // ---- warp softmax over per-lane scores ----
    float m0 = s0, m1 = s1;
    #pragma unroll
    for (int o = 16; o; o >>= 1) {
        m0 = fmaxf(m0, __shfl_xor_sync(0xffffffffu, m0, o));
        m1 = fmaxf(m1, __shfl_xor_sync(0xffffffffu, m1, o));
    }
    float e0 = __expf(s0 - m0), e1 = __expf(s1 - m1);
    float Z0 = e0, Z1 = e1;
    #pragma unroll
    for (int o = 16; o; o >>= 1) {
        Z0 += __shfl_xor_sync(0xffffffffu, Z0, o);
        Z1 += __shfl_xor_sync(0xffffffffu, Z1, o);
    }
    float w0 = e0 * (1.f / Z0), w1 = e1 * (1.f / Z1);
    if (lane < 20)
        wavg[lane] = 0.5f * (w0 + w1);

    // ---- phase 2: weighted sum (kv reloads hit L1/L2); no final divide ----
    unsigned long long av0[5], av1[5];
    #pragma unroll
    for (int u = 0; u < 5; u++) { av0[u] = 0ull; av1[u] = 0ull; }
    unsigned rem = validbits;
    while (rem) {
        int n = __ffs(rem) - 1;
        rem &= rem - 1;
        float a = __shfl_sync(0xffffffffu, w0, n);
        float c = __shfl_sync(0xffffffffu, w1, n);
        unsigned long long kv2[5];
        load_kv5(nf + (b * NNEI + n) * NFEAT, ntf + (b * NNEI + n) * NTIME, wbase, kv2);
        unsigned long long ad = pk2(a, a), cd = pk2(c, c);
        #pragma unroll
        for (int u = 0; u < 5; u++) { fma2(av0[u], ad, kv2[u]); fma2(av1[u], cd, kv2[u]); }
    }

    float* mb = g_m + b * 544;
    #pragma unroll
    for (int u = 0; u < 5; u++) {
        int c0 = wbase + 64 * u;
        if (c0 < 272) {
            *(float2*)(mb + c0) = upk2(av0[u]);
            *(float2*)(mb + 272 + c0) = upk2(av1[u]);
        }
    }
}

// ---------------- K4: out = m @ Pv + bo2; 8 batches/warp; Pv AND m staged; unroll-2 k loop ----------------
__global__ __launch_bounds__(256, 2) void k4_out(float* __restrict__ d_out) {
    extern __shared__ float sm[];
    float* Pvs = sm;                   // 136*128 = 17408 floats (k-tile of Pv)
    float* ms  = sm + 17408;           // 64*136  =  8704 floats (k-tile of m)
    int tid = threadIdx.x;
    int warp = tid >> 5, lane = tid & 31;
    size_t B0 = (size_t)blockIdx.x * 64;
    int lb = warp * 8;
    size_t b0 = B0 + lb;
    unsigned long long acc[8][2];
    #pragma unroll
    for (int i = 0; i < 8; i++) { acc[i][0] = 0ull; acc[i][1] = 0ull; }
    int wbase = lane * 2;
    #pragma unroll 1
    for (int kt = 0; kt < 4; kt++) {
        if (kt) __syncthreads();
        {   // stage Pv k-tile
            const float4* src = (const float4*)(g_Pv + kt * 136 * 128);
            for (int i = tid; i < 136 * 128 / 4; i += 256)
                ((float4*)Pvs)[i] = src[i];
        }
        {   // stage m k-tile
            for (int i = tid; i < 64 * 34; i += 256) {
                int bi = i / 34, c4 = i % 34;
                ((float4*)ms)[bi * 34 + c4] =
                    *(const float4*)(g_m + (B0 + bi) * 544 + kt * 136 + c4 * 4);
            }
        }
        __syncthreads();
        #pragma unroll 2
        for (int k = 0; k < 136; k += 4) {
            float4 xv[8];
            #pragma unroll
            for (int i = 0; i < 8; i++)
                xv[i] = *(const float4*)&ms[(lb + i) * 136 + k];
            #pragma unroll
            for (int q = 0; q < 4; q++) {
                unsigned long long w0 = *(const unsigned long long*)&Pvs[(k + q) * 128 + wbase];
                unsigned long long w1 = *(const unsigned long long*)&Pvs[(k + q) * 128 + wbase + 64];
                #pragma unroll
                for (int i = 0; i < 8; i++) {
                    float x = (q == 0) ? xv[i].x : (q == 1) ? xv[i].y : (q == 2) ? xv[i].z : xv[i].w;
                    unsigned long long xd = pk2(x, x);
                    fma2(acc[i][0], xd, w0);
                    fma2(acc[i][1], xd, w1);
                }
            }
        }
    }
    #pragma unroll
    for (int u = 0; u < 2; u++) {
        int c0 = lane * 2 + 64 * u;
        if (c0 < 100) {
            float bx = g_bo2[c0];
            float by = (c0 + 1 < 100) ? g_bo2[c0 + 1] : 0.f;
            #pragma unroll
            for (int i = 0; i < 8; i++) {
                float2 v = upk2(acc[i][u]);
                bool inv = g_invalid[b0 + i];
                v.x = inv ? 0.f : (v.x + bx);
                v.y = inv ? 0.f : (v.y + by);
                if (c0 + 1 < 100)
                    *(float2*)(d_out + (b0 + i) * 100 + c0) = v;
                else
                    d_out[(b0 + i) * 100 + c0] = v.x;
            }
        }
    }
}

extern "C" void kernel_launch(void* const* d_in, const int* in_sizes, int n_in,
                              void* d_out, int out_size) {
    (void)in_sizes; (void)n_in; (void)out_size;
    const float* st   = (const float*)d_in[0];
    const float* nf   = (const float*)d_in[1];
    const float* ntf  = (const float*)d_in[2];
    const void*  mask = d_in[3];
    const float* Wq   = (const float*)d_in[4];
    const float* Wk   = (const float*)d_in[5];
    const float* Wv   = (const float*)d_in[6];
    const float* b_in = (const float*)d_in[7];
    const float* Wo   = (const float*)d_in[8];
    const float* bo   = (const float*)d_in[9];
    float* out = (float*)d_out;

    cudaFuncSetAttribute(k1_qproj, cudaFuncAttributeMaxDynamicSharedMemorySize, 51200);
    cudaFuncSetAttribute(k2_aproj, cudaFuncAttributeMaxDynamicSharedMemorySize, 70400);
    cudaFuncSetAttribute(k4_out,   cudaFuncAttributeMaxDynamicSharedMemorySize, 104448);

    setup_kernel<<<272, 256>>>(Wq, Wk, Wv, b_in, Wo, bo, (const unsigned int*)mask);
    k1_qproj<<<BATCH / 64, 256, 51200>>>(st, b_in);
    k2_aproj<<<dim3(BATCH / 32, 2), 256, 70400>>>();
    k3_attn<<<BATCH / 4, 128>>>(nf, ntf, mask, out);
    k4_out<<<BATCH / 64, 256, 104448>>>(out);
}